// round 2
// baseline (speedup 1.0000x reference)
#include <cuda_runtime.h>
#include <math.h>

#define Bz   4
#define Sz   4096
#define Dz   1024
#define Hn   16
#define HDn  64
#define En   8
#define HIDz 4096
#define Tz   (Bz*Sz)
#define MAXROWS (2*Tz + En*128)

// ---------------- scratch (static device globals; no allocs allowed) -------
__device__ float g_XC  [(size_t)Tz*Dz];
__device__ float g_QKV [(size_t)Tz*3*Dz];
__device__ float g_AO  [(size_t)Tz*Dz];
__device__ float g_PROJ[(size_t)Tz*Dz];
__device__ float g_X1  [(size_t)Tz*Dz];
__device__ float g_WIN [(size_t)Dz*3*Dz];
__device__ float g_WOUT[(size_t)Dz*Dz];
__device__ float g_CT  [(size_t)3*Dz*Dz];
__device__ float g_WCONV[(size_t)3*Dz*Dz];
__device__ float g_H   [(size_t)MAXROWS*HIDz];
__device__ float g_YB  [(size_t)Tz*2*Dz];
__device__ int   g_counts[En];
__device__ int   g_offsets[En];
__device__ int   g_cursor[En];
__device__ int   g_rows_token[MAXROWS];
__device__ float g_rows_w[MAXROWS];
__device__ int   g_rows_slot[MAXROWS];
__device__ int   g_te[Tz][2];
__device__ float g_tw[Tz][2];

// ---------------- small helpers -------------------------------------------
__device__ __forceinline__ float warpsum(float v) {
    #pragma unroll
    for (int o = 16; o; o >>= 1) v += __shfl_xor_sync(0xffffffffu, v, o);
    return v;
}

// ---------------- misc kernels --------------------------------------------
__global__ void k_zero_counts() {
    if (threadIdx.x < En) g_counts[threadIdx.x] = 0;
}

// out[C x R] = in[R x C]^T
__global__ void k_transpose(const float* __restrict__ in, float* __restrict__ out,
                            int R, int C) {
    __shared__ float tile[32][33];
    int rc = blockIdx.y * 32, cc = blockIdx.x * 32;
    int x = threadIdx.x, y = threadIdx.y;
    #pragma unroll
    for (int i = 0; i < 32; i += 8)
        tile[y + i][x] = in[(size_t)(rc + y + i) * C + cc + x];
    __syncthreads();
    #pragma unroll
    for (int i = 0; i < 32; i += 8)
        out[(size_t)(cc + y + i) * R + rc + x] = tile[x][y + i];
}

// WCONV[(k*D+di)*D + do] = CT[(di*3+k)*D + do]
__global__ void k_conv_reorder() {
    int dout = blockIdx.x * 256 + threadIdx.x;  // 0..1023
    int rout = blockIdx.y;                      // 0..3071
    int k = rout >> 10, di = rout & (Dz - 1);
    g_WCONV[(size_t)rout * Dz + dout] = g_CT[(size_t)(di * 3 + k) * Dz + dout];
}

// ---------------- GEMM core (128x128x16 tiles, 256 thr, 8x8 micro) --------
// conv: C = sum_k Xshift_k @ Wk  (K = 3*D, A gathered with seq shift)
__global__ void __launch_bounds__(256) k_conv_gemm(const float* __restrict__ X,
                                                   const float* __restrict__ cb) {
    __shared__ float As[16][128];
    __shared__ float Bs[16][128];
    int tid = threadIdx.x;
    int bm = blockIdx.y * 128, bn = blockIdx.x * 128;
    int ar = tid >> 2, ac = (tid & 3) * 4;
    int br = tid >> 5, bc = (tid & 31) * 4;
    int ty = tid >> 4, tx = tid & 15;
    float acc[8][8] = {};
    for (int k0 = 0; k0 < 3 * Dz; k0 += 16) {
        int tap = k0 >> 10;
        int di0 = k0 & (Dz - 1);
        #pragma unroll
        for (int i = 0; i < 2; i++) {
            int r = ar + i * 64;
            int t = bm + r;
            int s = t & (Sz - 1);
            int srow = s + tap - 1;
            float4 v = make_float4(0.f, 0.f, 0.f, 0.f);
            if ((unsigned)srow < (unsigned)Sz)
                v = *(const float4*)(X + (size_t)(t - s + srow) * Dz + di0 + ac);
            As[ac + 0][r] = v.x; As[ac + 1][r] = v.y;
            As[ac + 2][r] = v.z; As[ac + 3][r] = v.w;
        }
        #pragma unroll
        for (int i = 0; i < 2; i++) {
            int r = br + i * 8;
            *(float4*)(&Bs[r][bc]) =
                *(const float4*)(g_WCONV + (size_t)(k0 + r) * Dz + bn + bc);
        }
        __syncthreads();
        #pragma unroll
        for (int kk = 0; kk < 16; kk++) {
            float a[8], b[8];
            *(float4*)(a)     = *(float4*)(&As[kk][ty * 8]);
            *(float4*)(a + 4) = *(float4*)(&As[kk][ty * 8 + 4]);
            *(float4*)(b)     = *(float4*)(&Bs[kk][tx * 8]);
            *(float4*)(b + 4) = *(float4*)(&Bs[kk][tx * 8 + 4]);
            #pragma unroll
            for (int i = 0; i < 8; i++)
                #pragma unroll
                for (int j = 0; j < 8; j++) acc[i][j] += a[i] * b[j];
        }
        __syncthreads();
    }
    #pragma unroll
    for (int i = 0; i < 8; i++) {
        size_t crow = (size_t)(bm + ty * 8 + i) * Dz + bn + tx * 8;
        #pragma unroll
        for (int j = 0; j < 8; j += 4) {
            float4 o;
            o.x = acc[i][j + 0] + cb[bn + tx * 8 + j + 0];
            o.y = acc[i][j + 1] + cb[bn + tx * 8 + j + 1];
            o.z = acc[i][j + 2] + cb[bn + tx * 8 + j + 2];
            o.w = acc[i][j + 3] + cb[bn + tx * 8 + j + 3];
            *(float4*)(g_XC + crow + j) = o;
        }
    }
}

// generic dense NN GEMM + bias:  C[M,N] = A[M,K] @ B[K,N] + bias
__global__ void __launch_bounds__(256) k_gemm_bias(const float* __restrict__ A,
                                                   const float* __restrict__ B,
                                                   const float* __restrict__ bias,
                                                   float* __restrict__ C,
                                                   int K, int lda, int ldb, int ldc) {
    __shared__ float As[16][128];
    __shared__ float Bs[16][128];
    int tid = threadIdx.x;
    int bm = blockIdx.y * 128, bn = blockIdx.x * 128;
    int ar = tid >> 2, ac = (tid & 3) * 4;
    int br = tid >> 5, bc = (tid & 31) * 4;
    int ty = tid >> 4, tx = tid & 15;
    float acc[8][8] = {};
    for (int k0 = 0; k0 < K; k0 += 16) {
        #pragma unroll
        for (int i = 0; i < 2; i++) {
            int r = ar + i * 64;
            float4 v = *(const float4*)(A + (size_t)(bm + r) * lda + k0 + ac);
            As[ac + 0][r] = v.x; As[ac + 1][r] = v.y;
            As[ac + 2][r] = v.z; As[ac + 3][r] = v.w;
        }
        #pragma unroll
        for (int i = 0; i < 2; i++) {
            int r = br + i * 8;
            *(float4*)(&Bs[r][bc]) =
                *(const float4*)(B + (size_t)(k0 + r) * ldb + bn + bc);
        }
        __syncthreads();
        #pragma unroll
        for (int kk = 0; kk < 16; kk++) {
            float a[8], b[8];
            *(float4*)(a)     = *(float4*)(&As[kk][ty * 8]);
            *(float4*)(a + 4) = *(float4*)(&As[kk][ty * 8 + 4]);
            *(float4*)(b)     = *(float4*)(&Bs[kk][tx * 8]);
            *(float4*)(b + 4) = *(float4*)(&Bs[kk][tx * 8 + 4]);
            #pragma unroll
            for (int i = 0; i < 8; i++)
                #pragma unroll
                for (int j = 0; j < 8; j++) acc[i][j] += a[i] * b[j];
        }
        __syncthreads();
    }
    #pragma unroll
    for (int i = 0; i < 8; i++) {
        size_t crow = (size_t)(bm + ty * 8 + i) * ldc + bn + tx * 8;
        #pragma unroll
        for (int j = 0; j < 8; j += 4) {
            float4 o;
            o.x = acc[i][j + 0] + bias[bn + tx * 8 + j + 0];
            o.y = acc[i][j + 1] + bias[bn + tx * 8 + j + 1];
            o.z = acc[i][j + 2] + bias[bn + tx * 8 + j + 2];
            o.w = acc[i][j + 3] + bias[bn + tx * 8 + j + 3];
            *(float4*)(C + crow + j) = o;
        }
    }
}

// ---------------- tiny attention (seq axis = B = 4) ------------------------
__global__ void k_attn() {
    int wg = blockIdx.x * 8 + (threadIdx.x >> 5);   // (n,h) pair id
    int lane = threadIdx.x & 31;
    int h = wg & (Hn - 1);
    int n = wg >> 4;
    const float scale = 0.125f;  // 1/sqrt(64)
    float2 q[Bz], k[Bz], v[Bz];
    #pragma unroll
    for (int l = 0; l < Bz; l++) {
        size_t base = ((size_t)l * Sz + n) * (3 * Dz) + h * HDn + lane * 2;
        q[l] = *(const float2*)(g_QKV + base);
        k[l] = *(const float2*)(g_QKV + base + Dz);
        v[l] = *(const float2*)(g_QKV + base + 2 * Dz);
    }
    float p[Bz][Bz];
    #pragma unroll
    for (int l = 0; l < Bz; l++)
        #pragma unroll
        for (int m = 0; m < Bz; m++) {
            float t = q[l].x * k[m].x + q[l].y * k[m].y;
            t = warpsum(t);
            p[l][m] = t * scale;
        }
    #pragma unroll
    for (int l = 0; l < Bz; l++) {
        float mx = fmaxf(fmaxf(p[l][0], p[l][1]), fmaxf(p[l][2], p[l][3]));
        float s = 0.f;
        #pragma unroll
        for (int m = 0; m < Bz; m++) { p[l][m] = expf(p[l][m] - mx); s += p[l][m]; }
        float inv = 1.f / s;
        #pragma unroll
        for (int m = 0; m < Bz; m++) p[l][m] *= inv;
    }
    #pragma unroll
    for (int l = 0; l < Bz; l++) {
        float2 o = make_float2(0.f, 0.f);
        #pragma unroll
        for (int m = 0; m < Bz; m++) {
            o.x += p[l][m] * v[m].x;
            o.y += p[l][m] * v[m].y;
        }
        *(float2*)(g_AO + ((size_t)l * Sz + n) * Dz + h * HDn + lane * 2) = o;
    }
}

// ---------------- LayerNorm kernels ---------------------------------------
__global__ void k_ln_add2(const float* __restrict__ A, const float* __restrict__ Bb,
                          const float* __restrict__ g, const float* __restrict__ be,
                          float* __restrict__ out) {
    int t = blockIdx.x, tid = threadIdx.x;
    float4 v = ((const float4*)(A + (size_t)t * Dz))[tid];
    float4 w = ((const float4*)(Bb + (size_t)t * Dz))[tid];
    v.x += w.x; v.y += w.y; v.z += w.z; v.w += w.w;
    float s = v.x + v.y + v.z + v.w;
    float q = v.x * v.x + v.y * v.y + v.z * v.z + v.w * v.w;
    s = warpsum(s); q = warpsum(q);
    __shared__ float ss[8], sq[8];
    int wid = tid >> 5;
    if ((tid & 31) == 0) { ss[wid] = s; sq[wid] = q; }
    __syncthreads();
    float S = 0.f, Q = 0.f;
    #pragma unroll
    for (int i = 0; i < 8; i++) { S += ss[i]; Q += sq[i]; }
    float mean = S * (1.f / Dz);
    float var  = Q * (1.f / Dz) - mean * mean;
    float rstd = rsqrtf(var + 1e-5f);
    float4 gg = ((const float4*)g)[tid];
    float4 bb = ((const float4*)be)[tid];
    float4 o;
    o.x = (v.x - mean) * rstd * gg.x + bb.x;
    o.y = (v.y - mean) * rstd * gg.y + bb.y;
    o.z = (v.z - mean) * rstd * gg.z + bb.z;
    o.w = (v.w - mean) * rstd * gg.w + bb.w;
    ((float4*)(out + (size_t)t * Dz))[tid] = o;
}

__global__ void k_ln_add3(const float* __restrict__ A,
                          const float* __restrict__ g, const float* __restrict__ be,
                          float* __restrict__ out) {
    int t = blockIdx.x, tid = threadIdx.x;
    float4 v  = ((const float4*)(A + (size_t)t * Dz))[tid];
    float4 y0 = ((const float4*)(g_YB + (size_t)t * 2 * Dz))[tid];
    float4 y1 = ((const float4*)(g_YB + (size_t)t * 2 * Dz + Dz))[tid];
    v.x += y0.x + y1.x; v.y += y0.y + y1.y;
    v.z += y0.z + y1.z; v.w += y0.w + y1.w;
    float s = v.x + v.y + v.z + v.w;
    float q = v.x * v.x + v.y * v.y + v.z * v.z + v.w * v.w;
    s = warpsum(s); q = warpsum(q);
    __shared__ float ss[8], sq[8];
    int wid = tid >> 5;
    if ((tid & 31) == 0) { ss[wid] = s; sq[wid] = q; }
    __syncthreads();
    float S = 0.f, Q = 0.f;
    #pragma unroll
    for (int i = 0; i < 8; i++) { S += ss[i]; Q += sq[i]; }
    float mean = S * (1.f / Dz);
    float var  = Q * (1.f / Dz) - mean * mean;
    float rstd = rsqrtf(var + 1e-5f);
    float4 gg = ((const float4*)g)[tid];
    float4 bb = ((const float4*)be)[tid];
    float4 o;
    o.x = (v.x - mean) * rstd * gg.x + bb.x;
    o.y = (v.y - mean) * rstd * gg.y + bb.y;
    o.z = (v.z - mean) * rstd * gg.z + bb.z;
    o.w = (v.w - mean) * rstd * gg.w + bb.w;
    ((float4*)(out + (size_t)t * Dz))[tid] = o;
}

// ---------------- MoE routing ---------------------------------------------
__global__ void k_gate(const float* __restrict__ gw, const float* __restrict__ gb) {
    int t = blockIdx.x * 8 + (threadIdx.x >> 5);
    int lane = threadIdx.x & 31;
    float acc[En] = {};
    const float* xr = g_X1 + (size_t)t * Dz;
    for (int d = lane; d < Dz; d += 32) {
        float xv = xr[d];
        #pragma unroll
        for (int e = 0; e < En; e++) acc[e] += xv * gw[d * En + e];
    }
    #pragma unroll
    for (int e = 0; e < En; e++) acc[e] = warpsum(acc[e]);
    if (lane == 0) {
        #pragma unroll
        for (int e = 0; e < En; e++) acc[e] += gb[e];
        int e0 = 0; float b0 = acc[0];
        #pragma unroll
        for (int e = 1; e < En; e++) if (acc[e] > b0) { b0 = acc[e]; e0 = e; }
        int e1 = -1; float b1v = -1e30f;
        #pragma unroll
        for (int e = 0; e < En; e++)
            if (e != e0 && acc[e] > b1v) { b1v = acc[e]; e1 = e; }
        float x1 = expf(b1v - b0);
        float inv = 1.f / (1.f + x1);
        g_te[t][0] = e0; g_te[t][1] = e1;
        g_tw[t][0] = inv; g_tw[t][1] = x1 * inv;
        atomicAdd(&g_counts[e0], 1);
        atomicAdd(&g_counts[e1], 1);
    }
}

__global__ void k_offsets() {
    if (threadIdx.x == 0) {
        int off = 0;
        for (int e = 0; e < En; e++) {
            g_offsets[e] = off;
            off += ((g_counts[e] + 127) >> 7) << 7;
            g_cursor[e] = 0;
        }
    }
}

__global__ void k_scatter() {
    int t = blockIdx.x * 256 + threadIdx.x;
    if (t >= Tz) return;
    #pragma unroll
    for (int slot = 0; slot < 2; slot++) {
        int e = g_te[t][slot];
        int pos = atomicAdd(&g_cursor[e], 1);
        int row = g_offsets[e] + pos;
        g_rows_token[row] = t;
        g_rows_w[row] = g_tw[t][slot];
        g_rows_slot[row] = slot;
    }
}

// ---------------- grouped MoE GEMMs ---------------------------------------
// H[row] = relu(X1[tok] @ w1[e] + b1[e])
__global__ void __launch_bounds__(256) k_moe1(const float* __restrict__ w1,
                                              const float* __restrict__ b1) {
    int e = blockIdx.z;
    int cnt = g_counts[e];
    int bm = blockIdx.y * 128;
    if (bm >= cnt) return;
    int off = g_offsets[e];
    int bn = blockIdx.x * 128;
    __shared__ float As[16][128];
    __shared__ float Bs[16][128];
    __shared__ int stok[128];
    int tid = threadIdx.x;
    if (tid < 128)
        stok[tid] = (bm + tid < cnt) ? g_rows_token[off + bm + tid] : -1;
    __syncthreads();
    int ar = tid >> 2, ac = (tid & 3) * 4;
    int br = tid >> 5, bc = (tid & 31) * 4;
    int ty = tid >> 4, tx = tid & 15;
    const float* B = w1 + (size_t)e * Dz * HIDz;
    float acc[8][8] = {};
    for (int k0 = 0; k0 < Dz; k0 += 16) {
        #pragma unroll
        for (int i = 0; i < 2; i++) {
            int r = ar + i * 64;
            int tok = stok[r];
            float4 v = make_float4(0.f, 0.f, 0.f, 0.f);
            if (tok >= 0)
                v = *(const float4*)(g_X1 + (size_t)tok * Dz + k0 + ac);
            As[ac + 0][r] = v.x; As[ac + 1][r] = v.y;
            As[ac + 2][r] = v.z; As[ac + 3][r] = v.w;
        }
        #pragma unroll
        for (int i = 0; i < 2; i++) {
            int r = br + i * 8;
            *(float4*)(&Bs[r][bc]) =
                *(const float4*)(B + (size_t)(k0 + r) * HIDz + bn + bc);
        }
        __syncthreads();
        #pragma unroll
        for (int kk = 0; kk < 16; kk++) {
            float a[8], b[8];
            *(float4*)(a)     = *(float4*)(&As[kk][ty * 8]);
            *(float4*)(a + 4) = *(float4*)(&As[kk][ty * 8 + 4]);
            *(float4*)(b)     = *(float4*)(&Bs[kk][tx * 8]);
            *(float4*)(b + 4) = *(float4*)(&Bs[kk][tx * 8 + 4]);
            #pragma unroll
            for (int i = 0; i < 8; i++)
                #pragma unroll
                for (int j = 0; j < 8; j++) acc[i][j] += a[i] * b[j];
        }
        __syncthreads();
    }
    const float* bias = b1 + (size_t)e * HIDz;
    #pragma unroll
    for (int i = 0; i < 8; i++) {
        int rl = ty * 8 + i;
        if (bm + rl >= cnt) continue;
        size_t crow = (size_t)(off + bm + rl) * HIDz + bn + tx * 8;
        #pragma unroll
        for (int j = 0; j < 8; j += 4) {
            float4 o;
            o.x = fmaxf(acc[i][j + 0] + bias[bn + tx * 8 + j + 0], 0.f);
            o.y = fmaxf(acc[i][j + 1] + bias[bn + tx * 8 + j + 1], 0.f);
            o.z = fmaxf(acc[i][j + 2] + bias[bn + tx * 8 + j + 2], 0.f);
            o.w = fmaxf(acc[i][j + 3] + bias[bn + tx * 8 + j + 3], 0.f);
            *(float4*)(g_H + crow + j) = o;
        }
    }
}

// YB[tok, slot] = w * (H[row] @ w2[e] + b2[e])
__global__ void __launch_bounds__(256) k_moe2(const float* __restrict__ w2,
                                              const float* __restrict__ b2) {
    int e = blockIdx.z;
    int cnt = g_counts[e];
    int bm = blockIdx.y * 128;
    if (bm >= cnt) return;
    int off = g_offsets[e];
    int bn = blockIdx.x * 128;
    __shared__ float As[16][128];
    __shared__ float Bs[16][128];
    int tid = threadIdx.x;
    int ar = tid >> 2, ac = (tid & 3) * 4;
    int br = tid >> 5, bc = (tid & 31) * 4;
    int ty = tid >> 4, tx = tid & 15;
    const float* B = w2 + (size_t)e * HIDz * Dz;
    float acc[8][8] = {};
    for (int k0 = 0; k0 < HIDz; k0 += 16) {
        #pragma unroll
        for (int i = 0; i < 2; i++) {
            int r = ar + i * 64;
            float4 v = make_float4(0.f, 0.f, 0.f, 0.f);
            if (bm + r < cnt)
                v = *(const float4*)(g_H + (size_t)(off + bm + r) * HIDz + k0 + ac);
            As[ac + 0][r] = v.x; As[ac + 1][r] = v.y;
            As[ac + 2][r] = v.z; As[ac + 3][r] = v.w;
        }
        #pragma unroll
        for (int i = 0; i < 2; i++) {
            int r = br + i * 8;
            *(float4*)(&Bs[r][bc]) =
                *(const float4*)(B + (size_t)(k0 + r) * Dz + bn + bc);
        }
        __syncthreads();
        #pragma unroll
        for (int kk = 0; kk < 16; kk++) {
            float a[8], b[8];
            *(float4*)(a)     = *(float4*)(&As[kk][ty * 8]);
            *(float4*)(a + 4) = *(float4*)(&As[kk][ty * 8 + 4]);
            *(float4*)(b)     = *(float4*)(&Bs[kk][tx * 8]);
            *(float4*)(b + 4) = *(float4*)(&Bs[kk][tx * 8 + 4]);
            #pragma unroll
            for (int i = 0; i < 8; i++)
                #pragma unroll
                for (int j = 0; j < 8; j++) acc[i][j] += a[i] * b[j];
        }
        __syncthreads();
    }
    const float* bias = b2 + (size_t)e * Dz;
    #pragma unroll
    for (int i = 0; i < 8; i++) {
        int rl = ty * 8 + i;
        int rg = off + bm + rl;
        if (bm + rl >= cnt) continue;
        int tok = g_rows_token[rg];
        int slot = g_rows_slot[rg];
        float w = g_rows_w[rg];
        size_t crow = ((size_t)tok * 2 + slot) * Dz + bn + tx * 8;
        #pragma unroll
        for (int j = 0; j < 8; j += 4) {
            float4 o;
            o.x = w * (acc[i][j + 0] + bias[bn + tx * 8 + j + 0]);
            o.y = w * (acc[i][j + 1] + bias[bn + tx * 8 + j + 1]);
            o.z = w * (acc[i][j + 2] + bias[bn + tx * 8 + j + 2]);
            o.w = w * (acc[i][j + 3] + bias[bn + tx * 8 + j + 3]);
            *(float4*)(g_YB + crow + j) = o;
        }
    }
}

// ---------------- launch ---------------------------------------------------
extern "C" void kernel_launch(void* const* d_in, const int* in_sizes, int n_in,
                              void* d_out, int out_size) {
    const float* x          = (const float*)d_in[0];
    const float* conv_w     = (const float*)d_in[1];
    const float* conv_b     = (const float*)d_in[2];
    const float* in_proj_w  = (const float*)d_in[3];
    const float* in_proj_b  = (const float*)d_in[4];
    const float* out_proj_w = (const float*)d_in[5];
    const float* out_proj_b = (const float*)d_in[6];
    const float* ln1_g      = (const float*)d_in[7];
    const float* ln1_b      = (const float*)d_in[8];
    const float* gate_w     = (const float*)d_in[9];
    const float* gate_b     = (const float*)d_in[10];
    const float* w1         = (const float*)d_in[11];
    const float* b1         = (const float*)d_in[12];
    const float* w2         = (const float*)d_in[13];
    const float* b2         = (const float*)d_in[14];
    const float* ln2_g      = (const float*)d_in[15];
    const float* ln2_b      = (const float*)d_in[16];
    float* out = (float*)d_out;

    float *pWIN, *pWOUT, *pCT, *pXC, *pQKV, *pAO, *pPROJ, *pX1;
    cudaGetSymbolAddress((void**)&pWIN,  g_WIN);
    cudaGetSymbolAddress((void**)&pWOUT, g_WOUT);
    cudaGetSymbolAddress((void**)&pCT,   g_CT);
    cudaGetSymbolAddress((void**)&pXC,   g_XC);
    cudaGetSymbolAddress((void**)&pQKV,  g_QKV);
    cudaGetSymbolAddress((void**)&pAO,   g_AO);
    cudaGetSymbolAddress((void**)&pPROJ, g_PROJ);
    cudaGetSymbolAddress((void**)&pX1,   g_X1);

    dim3 tb(32, 8);
    k_zero_counts<<<1, 32>>>();
    // weight prep
    k_transpose<<<dim3(Dz / 32, 3 * Dz / 32), tb>>>(in_proj_w, pWIN, 3 * Dz, Dz);
    k_transpose<<<dim3(Dz / 32, Dz / 32), tb>>>(out_proj_w, pWOUT, Dz, Dz);
    k_transpose<<<dim3(3 * Dz / 32, Dz / 32), tb>>>(conv_w, pCT, Dz, 3 * Dz);
    k_conv_reorder<<<dim3(Dz / 256, 3 * Dz), 256>>>();
    // conv
    k_conv_gemm<<<dim3(Dz / 128, Tz / 128), 256>>>(x, conv_b);
    // qkv
    k_gemm_bias<<<dim3(3 * Dz / 128, Tz / 128), 256>>>(pXC, pWIN, in_proj_b, pQKV,
                                                       Dz, Dz, 3 * Dz, 3 * Dz);
    // attention (tiny seq=B=4)
    k_attn<<<(Sz * Hn) / 8, 256>>>();
    // out_proj
    k_gemm_bias<<<dim3(Dz / 128, Tz / 128), 256>>>(pAO, pWOUT, out_proj_b, pPROJ,
                                                   Dz, Dz, Dz, Dz);
    // residual + LN1
    k_ln_add2<<<Tz, 256>>>(pXC, pPROJ, ln1_g, ln1_b, pX1);
    // MoE routing
    k_gate<<<Tz / 8, 256>>>(gate_w, gate_b);
    k_offsets<<<1, 32>>>();
    k_scatter<<<Tz / 256, 256>>>();
    // grouped expert GEMMs
    k_moe1<<<dim3(HIDz / 128, Tz / 128, En), 256>>>(w1, b1);
    k_moe2<<<dim3(Dz / 128, Tz / 128, En), 256>>>(w2, b2);
    // residual + LN2 -> output
    k_ln_add3<<<Tz, 256>>>(pX1, ln2_g, ln2_b, out);
}